// round 5
// baseline (speedup 1.0000x reference)
#include <cuda_runtime.h>
#include <cuda_fp16.h>

#define FULL 0xFFFFFFFFu

constexpr int B  = 16;
constexpr int T  = 512;
constexpr int C  = 3;
constexpr int V  = 16;
constexpr int H  = 128;
constexpr int NC = 12;

constexpr int NWARPS     = 8;
constexpr int THREADS    = NWARPS * 32;
constexpr int BLK_PER_B  = 37;
constexpr int NBLK       = B * BLK_PER_B;      // 592 = 4 blocks/SM * 148 SMs
constexpr int WARPS_PER_B = BLK_PER_B * NWARPS; // 296

constexpr int W2C_STRIDE = 132;                 // halves; 264B col stride, LDS.64 conflict-free

// smem layout (bytes)
constexpr int SM_W2C_BYTES = H * W2C_STRIDE * 2;          // 33792
constexpr int SM_C2_OFF    = SM_W2C_BYTES;                // 128 f32
constexpr int SM_INV2_OFF  = SM_C2_OFF + H * 4;           // 128 f32
constexpr int SM_SACC_OFF  = SM_INV2_OFF + H * 4;         // 128 f32
constexpr int SM_BYTES     = SM_SACC_OFF + H * 4;         // ~35.3 KB -> 4 blocks/SM

__device__ float    g_acc[B * H];   // zero-init; reset by last block each call
__device__ unsigned g_ctr;          // ticket counter; reset by last block each call

// gather selected fp16 columns (mask m, group g) into 4 fp32 accumulators
__device__ __forceinline__ void accm(const __half* __restrict__ colb, int g, unsigned m,
                                     float* __restrict__ a) {
    while (m) {                                  // warp-uniform (ballot result)
        int bit = __ffs(m) - 1;
        m &= m - 1;
        uint2 u = *reinterpret_cast<const uint2*>(colb + (g * 32 + bit) * W2C_STRIDE);
        __half2 h0 = *reinterpret_cast<__half2*>(&u.x);
        __half2 h1 = *reinterpret_cast<__half2*>(&u.y);
        float2 f0 = __half22float2(h0);
        float2 f1 = __half22float2(h1);
        a[0] += f0.x; a[1] += f0.y; a[2] += f1.x; a[3] += f1.y;
    }
}

// LIF2 over 4 steps; h2 inputs reconstructed from A,B1,B2,B3; returns spike count
__device__ __forceinline__ float lif2(float A, float Bb1, float Bb2, float Bb3, float cc) {
    float base = A + cc;
    float vv = base * 0.5f;
    float cnt = 0.f;
    if (vv >= 0.5f) { cnt += 1.f; vv = 0.f; }
    float h = base + Bb3;
    vv = vv + (h - vv) * 0.5f;
    if (vv >= 0.5f) { cnt += 1.f; vv = 0.f; }
    h = base + Bb2;
    vv = vv + (h - vv) * 0.5f;
    if (vv >= 0.5f) { cnt += 1.f; vv = 0.f; }
    h = base + Bb3 + Bb1;
    vv = vv + (h - vv) * 0.5f;
    if (vv >= 0.5f) cnt += 1.f;
    return cnt;
}

__global__ void __launch_bounds__(THREADS, 4)
snn_main(const float* __restrict__ x,
         const float* __restrict__ w1, const float* __restrict__ b1,
         const float* __restrict__ g1, const float* __restrict__ be1,
         const float* __restrict__ m1, const float* __restrict__ rv1,
         const float* __restrict__ w2, const float* __restrict__ b2,
         const float* __restrict__ g2, const float* __restrict__ be2,
         const float* __restrict__ m2, const float* __restrict__ rv2,
         const float* __restrict__ wc, const float* __restrict__ bc,
         float* __restrict__ out) {
    extern __shared__ __align__(16) unsigned char smraw[];
    __half* w2c  = reinterpret_cast<__half*>(smraw);
    float*  c2s  = reinterpret_cast<float*>(smraw + SM_C2_OFF);
    float*  inv2s = reinterpret_cast<float*>(smraw + SM_INV2_OFF);
    float*  sacc = reinterpret_cast<float*>(smraw + SM_SACC_OFF);

    const int tid  = threadIdx.x;
    const int warp = tid >> 5, lane = tid & 31;

    // ---- fold BN2 into W2 (fp16, column-major) + c2; zero SACC ----
    if (tid < H) {
        float inv2 = g2[tid] * rsqrtf(rv2[tid] + 1e-5f);
        inv2s[tid] = inv2;
        c2s[tid]   = (b2[tid] - m2[tid]) * inv2 + be2[tid];
        sacc[tid]  = 0.f;
    }
    __syncthreads();
    for (int idx = tid; idx < H * H; idx += THREADS) {
        int o = idx & (H - 1), p = idx >> 7;     // coalesced global read of w2
        w2c[o * W2C_STRIDE + p] = __float2half_rn(w2[p * H + o] * inv2s[p]);
    }
    __syncthreads();

    // ---- per-thread folded fc1 params (channel o = g*32 + lane) ----
    float w1a[4], w1b[4], w1c[4], c1r[4];
#pragma unroll
    for (int g = 0; g < 4; g++) {
        int o = g * 32 + lane;
        float inv1 = g1[o] * rsqrtf(rv1[o] + 1e-5f);
        w1a[g] = w1[o * 3 + 0] * inv1;
        w1b[g] = w1[o * 3 + 1] * inv1;
        w1c[g] = w1[o * 3 + 2] * inv1;
        c1r[g] = (b1[o] - m1[o]) * inv1 + be1[o];
    }
    const float c2x = c2s[4 * lane + 0];
    const float c2y = c2s[4 * lane + 1];
    const float c2z = c2s[4 * lane + 2];
    const float c2w = c2s[4 * lane + 3];
    const __half* colb = w2c + 4 * lane;

    // ---- uniform position span within this batch element ----
    const int bb = blockIdx.x / BLK_PER_B;
    const int w  = (blockIdx.x % BLK_PER_B) * NWARPS + warp;   // [0, 296)
    int p  = (w * 1024) / BLK_PER_B;          // = w*8192/296, local position
    int ep = ((w + 1) * 1024) / BLK_PER_B;
    const float* xb = x + (size_t)bb * (T * C * V);

    float f0 = 0.f, f1 = 0.f, f2 = 0.f, f3 = 0.f;

    while (p < ep) {
        int row = p >> 4;                      // (t) row: 48 contiguous floats
        const float* rp = xb + row * (C * V);
        float ld0 = rp[lane];                  // lanes 0-15: c0[v], 16-31: c1[v]
        float ld1 = (lane < 16) ? rp[32 + lane] : 0.f;   // c2[v]
        int ve = min(16, ep - (row << 4));

        for (int v = p - (row << 4); v < ve; v++) {
            float x0 = __shfl_sync(FULL, ld0, v);
            float x1 = __shfl_sync(FULL, ld0, v + 16);
            float x2 = __shfl_sync(FULL, ld1, v);

            float aA[4]  = {0, 0, 0, 0};
            float aB1[4] = {0, 0, 0, 0};
            float aB2[4] = {0, 0, 0, 0};
            float aB3[4] = {0, 0, 0, 0};
#pragma unroll
            for (int g = 0; g < 4; g++) {
                float h = fmaf(w1a[g], x0, fmaf(w1b[g], x1, fmaf(w1c[g], x2, c1r[g])));
                // LIF1 with constant input: category = first-spike step
                int cat;
                float vv = h * 0.5f;
                if (vv >= 0.5f) cat = 4;                          // 1111
                else {
                    vv = vv + (h - vv) * 0.5f;
                    if (vv >= 0.5f) cat = 3;                      // 0101
                    else {
                        vv = vv + (h - vv) * 0.5f;
                        if (vv >= 0.5f) cat = 2;                  // 0010
                        else {
                            vv = vv + (h - vv) * 0.5f;
                            cat = (vv >= 0.5f) ? 1 : 0;           // 0001 / 0000
                        }
                    }
                }
                unsigned bl0 = __ballot_sync(FULL, cat & 1);
                unsigned bl1 = __ballot_sync(FULL, cat & 2);
                unsigned bl2 = __ballot_sync(FULL, cat & 4);
                accm(colb, g, bl2,         aA);    // cat 4
                accm(colb, g, bl0 & bl1,   aB3);   // cat 3
                accm(colb, g, bl1 & ~bl0,  aB2);   // cat 2
                accm(colb, g, bl0 & ~bl1,  aB1);   // cat 1
            }

            f0 += lif2(aA[0], aB1[0], aB2[0], aB3[0], c2x);
            f1 += lif2(aA[1], aB1[1], aB2[1], aB3[1], c2y);
            f2 += lif2(aA[2], aB1[2], aB2[2], aB3[2], c2z);
            f3 += lif2(aA[3], aB1[3], aB2[3], aB3[3], c2w);
        }
        p = (row << 4) + ve;
    }

    // counts are small integers -> fp32-exact, order-independent (deterministic)
    atomicAdd(&sacc[4 * lane + 0], f0);
    atomicAdd(&sacc[4 * lane + 1], f1);
    atomicAdd(&sacc[4 * lane + 2], f2);
    atomicAdd(&sacc[4 * lane + 3], f3);
    __syncthreads();
    if (tid < H) atomicAdd(&g_acc[bb * H + tid], sacc[tid]);

    // ---- last-block epilogue: feat -> classifier, then reset state ----
    __shared__ unsigned s_ticket;
    __threadfence();
    __syncthreads();
    if (tid == 0) s_ticket = atomicAdd(&g_ctr, 1u);
    __syncthreads();
    if (s_ticket == NBLK - 1) {
        __threadfence();
        float* feat = reinterpret_cast<float*>(smraw);   // reuse w2c area (gather done)
        for (int i = tid; i < B * H; i += THREADS) {
            float v = __ldcg(&g_acc[i]);
            feat[i] = v * (1.f / (4.f * (float)(T * V)));
            g_acc[i] = 0.f;                              // reset for next call
        }
        __syncthreads();
        if (tid < B * NC) {
            int b = tid / NC, n = tid % NC;
            float s = bc[n];
#pragma unroll 8
            for (int pch = 0; pch < H; pch++)
                s = fmaf(wc[n * H + pch], feat[b * H + pch], s);
            out[b * NC + n] = s;
        }
        if (tid == 0) atomicExch(&g_ctr, 0u);            // reset for next call
    }
}

extern "C" void kernel_launch(void* const* d_in, const int* in_sizes, int n_in,
                              void* d_out, int out_size) {
    const float* x   = (const float*)d_in[0];
    const float* w1  = (const float*)d_in[1];
    const float* b1  = (const float*)d_in[2];
    const float* g1  = (const float*)d_in[3];
    const float* be1 = (const float*)d_in[4];
    const float* m1  = (const float*)d_in[5];
    const float* rv1 = (const float*)d_in[6];
    const float* w2  = (const float*)d_in[7];
    const float* b2  = (const float*)d_in[8];
    const float* g2  = (const float*)d_in[9];
    const float* be2 = (const float*)d_in[10];
    const float* m2  = (const float*)d_in[11];
    const float* rv2 = (const float*)d_in[12];
    const float* wc  = (const float*)d_in[13];
    const float* bc  = (const float*)d_in[14];

    cudaFuncSetAttribute(snn_main, cudaFuncAttributeMaxDynamicSharedMemorySize, SM_BYTES);

    snn_main<<<NBLK, THREADS, SM_BYTES>>>(x, w1, b1, g1, be1, m1, rv1,
                                          w2, b2, g2, be2, m2, rv2,
                                          wc, bc, (float*)d_out);
}

// round 6
// speedup vs baseline: 1.6584x; 1.6584x over previous
#include <cuda_runtime.h>

#define FULL 0xFFFFFFFFu

constexpr int B  = 16;
constexpr int T  = 512;
constexpr int C  = 3;
constexpr int V  = 16;
constexpr int H  = 128;
constexpr int NC = 12;

constexpr int NWARPS    = 8;
constexpr int THREADS   = NWARPS * 32;
constexpr int BLK_PER_B = 27;
constexpr int NBLK      = B * BLK_PER_B;        // 432 = one wave at 3 blocks/SM

// shared layout (floats)
constexpr int W2C_STRIDE = 132;                 // 528B col stride; LDS.128 conflict-free
constexpr int SM_W2C  = 0;                      // [128 cols][132]
constexpr int SM_C2   = SM_W2C + H * W2C_STRIDE;
constexpr int SM_INV2 = SM_C2 + H;
constexpr int SM_SACC = SM_INV2 + H;
constexpr int SM_TOT  = SM_SACC + H;
constexpr int SM_BYTES = SM_TOT * 4;            // ~69 KB -> 3 blocks/SM

// LIF1 closed-form thresholds: v_k = (1 - 2^-k) * h  (no-spike trajectory), spike iff v_k >= 0.5
__device__ __constant__ const float TH4f = 1.0f;            // 0.5 / 0.5
constexpr float TH3 = 2.0f / 3.0f;                           // 0.5 / 0.75
constexpr float TH2 = 4.0f / 7.0f;                           // 0.5 / 0.875
constexpr float TH1 = 8.0f / 15.0f;                          // 0.5 / 0.9375

__device__ float    g_acc[B * H];   // zero-init; reset by last block each call
__device__ unsigned g_ctr;          // ticket; reset by last block each call

// packed f32x2 helpers
__device__ __forceinline__ void addx2(unsigned long long& acc, unsigned long long v) {
    asm("add.rn.f32x2 %0, %0, %1;" : "+l"(acc) : "l"(v));
}
__device__ __forceinline__ void unpk(unsigned long long v, float& lo, float& hi) {
    asm("mov.b64 {%0, %1}, %2;" : "=f"(lo), "=f"(hi) : "l"(v));
}

// accumulate selected W2' columns (warp-uniform mask m, group g) into packed accumulators
__device__ __forceinline__ void accm(const float* __restrict__ colb, int g, unsigned m,
                                     unsigned long long& xy, unsigned long long& zw) {
    while (m) {
        int bit = __ffs(m) - 1;
        m &= m - 1;
        const ulonglong2 cv =
            *reinterpret_cast<const ulonglong2*>(colb + (g * 32 + bit) * W2C_STRIDE);
        addx2(xy, cv.x);
        addx2(zw, cv.y);
    }
}

// branch-free LIF2 over 4 steps; returns spike count
__device__ __forceinline__ float lif2(float A, float Bb1, float Bb2, float Bb3, float cc) {
    float base = A + cc;
    float h2 = base + Bb3;
    float h3 = base + Bb2;
    float h4 = h2 + Bb1;

    float v = base * 0.5f;
    bool s = v >= 0.5f;
    int cnt = s;
    v = s ? 0.f : v;

    v = fmaf(h2 - v, 0.5f, v);
    s = v >= 0.5f; cnt += s; v = s ? 0.f : v;

    v = fmaf(h3 - v, 0.5f, v);
    s = v >= 0.5f; cnt += s; v = s ? 0.f : v;

    v = fmaf(h4 - v, 0.5f, v);
    cnt += (v >= 0.5f);
    return (float)cnt;
}

__global__ void __launch_bounds__(THREADS, 3)
snn_main(const float* __restrict__ x,
         const float* __restrict__ w1, const float* __restrict__ b1,
         const float* __restrict__ g1, const float* __restrict__ be1,
         const float* __restrict__ m1, const float* __restrict__ rv1,
         const float* __restrict__ w2, const float* __restrict__ b2,
         const float* __restrict__ g2, const float* __restrict__ be2,
         const float* __restrict__ m2, const float* __restrict__ rv2,
         const float* __restrict__ wc, const float* __restrict__ bc,
         float* __restrict__ out) {
    extern __shared__ float sm[];
    const int tid  = threadIdx.x;
    const int warp = tid >> 5, lane = tid & 31;

    // ---- fold BN2 into W2 (fp32, column-major) + c2; zero SACC ----
    if (tid < H) {
        float inv2 = g2[tid] * rsqrtf(rv2[tid] + 1e-5f);
        sm[SM_INV2 + tid] = inv2;
        sm[SM_C2 + tid]   = (b2[tid] - m2[tid]) * inv2 + be2[tid];
        sm[SM_SACC + tid] = 0.f;
    }
    __syncthreads();
    for (int idx = tid; idx < H * H; idx += THREADS) {
        int o = idx & (H - 1), p = idx >> 7;    // coalesced global read of w2
        sm[SM_W2C + o * W2C_STRIDE + p] = w2[p * H + o] * sm[SM_INV2 + p];
    }
    __syncthreads();

    // ---- per-thread folded fc1 params (channel o = g*32 + lane) ----
    float w1a[4], w1b[4], w1c[4], c1r[4];
#pragma unroll
    for (int g = 0; g < 4; g++) {
        int o = g * 32 + lane;
        float inv1 = g1[o] * rsqrtf(rv1[o] + 1e-5f);
        w1a[g] = w1[o * 3 + 0] * inv1;
        w1b[g] = w1[o * 3 + 1] * inv1;
        w1c[g] = w1[o * 3 + 2] * inv1;
        c1r[g] = (b1[o] - m1[o]) * inv1 + be1[o];
    }
    const float c2x = sm[SM_C2 + 4 * lane + 0];
    const float c2y = sm[SM_C2 + 4 * lane + 1];
    const float c2z = sm[SM_C2 + 4 * lane + 2];
    const float c2w = sm[SM_C2 + 4 * lane + 3];
    const float* colb = sm + SM_W2C + 4 * lane;

    // ---- uniform position span within this batch element ----
    const int bb = blockIdx.x / BLK_PER_B;
    const int w  = (blockIdx.x % BLK_PER_B) * NWARPS + warp;   // [0, 216)
    int p  = (w * 1024) / BLK_PER_B;            // = w*8192/216
    int ep = ((w + 1) * 1024) / BLK_PER_B;
    const float* xb = x + (size_t)bb * (T * C * V);

    float f0 = 0.f, f1 = 0.f, f2 = 0.f, f3 = 0.f;

    while (p < ep) {
        int row = p >> 4;                       // t-row: 48 contiguous floats
        const float* rp = xb + row * (C * V);
        float ld0 = rp[lane];                   // lanes 0-15: c0[v], 16-31: c1[v]
        float ld1 = (lane < 16) ? rp[32 + lane] : 0.f;   // c2[v]
        int ve = min(16, ep - (row << 4));

        for (int v = p - (row << 4); v < ve; v++) {
            float x0 = __shfl_sync(FULL, ld0, v);
            float x1 = __shfl_sync(FULL, ld0, v + 16);
            float x2 = __shfl_sync(FULL, ld1, v);

            // h per group + branch-free category ballots
            float hh[4];
            unsigned m4[4], m3[4], m2m[4], m1m[4];
#pragma unroll
            for (int g = 0; g < 4; g++)
                hh[g] = fmaf(w1a[g], x0, fmaf(w1b[g], x1, fmaf(w1c[g], x2, c1r[g])));
#pragma unroll
            for (int g = 0; g < 4; g++) {
                unsigned b4 = __ballot_sync(FULL, hh[g] >= 1.0f);
                unsigned b3 = __ballot_sync(FULL, hh[g] >= TH3);
                unsigned b2 = __ballot_sync(FULL, hh[g] >= TH2);
                unsigned b1 = __ballot_sync(FULL, hh[g] >= TH1);
                m4[g]  = b4;            // 1111
                m3[g]  = b3 ^ b4;       // 0101
                m2m[g] = b2 ^ b3;       // 0010
                m1m[g] = b1 ^ b2;       // 0001
            }

            unsigned long long Axy = 0, Azw = 0, B1xy = 0, B1zw = 0,
                               B2xy = 0, B2zw = 0, B3xy = 0, B3zw = 0;
#pragma unroll
            for (int g = 0; g < 4; g++) {
                accm(colb, g, m4[g],  Axy,  Azw);
                accm(colb, g, m3[g],  B3xy, B3zw);
                accm(colb, g, m2m[g], B2xy, B2zw);
                accm(colb, g, m1m[g], B1xy, B1zw);
            }

            float Ax, Ay, Az, Aw, B1x, B1y, B1z, B1w;
            float B2x, B2y, B2z, B2w, B3x, B3y, B3z, B3w;
            unpk(Axy, Ax, Ay);    unpk(Azw, Az, Aw);
            unpk(B1xy, B1x, B1y); unpk(B1zw, B1z, B1w);
            unpk(B2xy, B2x, B2y); unpk(B2zw, B2z, B2w);
            unpk(B3xy, B3x, B3y); unpk(B3zw, B3z, B3w);

            f0 += lif2(Ax, B1x, B2x, B3x, c2x);
            f1 += lif2(Ay, B1y, B2y, B3y, c2y);
            f2 += lif2(Az, B1z, B2z, B3z, c2z);
            f3 += lif2(Aw, B1w, B2w, B3w, c2w);
        }
        p = (row << 4) + ve;
    }

    // counts are small integers -> fp32-exact, order-independent (deterministic)
    atomicAdd(&sm[SM_SACC + 4 * lane + 0], f0);
    atomicAdd(&sm[SM_SACC + 4 * lane + 1], f1);
    atomicAdd(&sm[SM_SACC + 4 * lane + 2], f2);
    atomicAdd(&sm[SM_SACC + 4 * lane + 3], f3);
    __syncthreads();
    if (tid < H) atomicAdd(&g_acc[bb * H + tid], sm[SM_SACC + tid]);

    // ---- last-block epilogue: feat -> classifier, reset state ----
    __shared__ unsigned s_ticket;
    __threadfence();
    __syncthreads();
    if (tid == 0) s_ticket = atomicAdd(&g_ctr, 1u);
    __syncthreads();
    if (s_ticket == NBLK - 1) {
        __threadfence();
        float* feat = sm;                        // reuse W2C area (gather done)
        for (int i = tid; i < B * H; i += THREADS) {
            float v = __ldcg(&g_acc[i]);
            feat[i] = v * (1.f / (4.f * (float)(T * V)));
            g_acc[i] = 0.f;                      // reset for next call
        }
        __syncthreads();
        if (tid < B * NC) {
            int b = tid / NC, n = tid % NC;
            float s = bc[n];
#pragma unroll 8
            for (int pch = 0; pch < H; pch++)
                s = fmaf(wc[n * H + pch], feat[b * H + pch], s);
            out[b * NC + n] = s;
        }
        if (tid == 0) atomicExch(&g_ctr, 0u);    // reset for next call
    }
}

extern "C" void kernel_launch(void* const* d_in, const int* in_sizes, int n_in,
                              void* d_out, int out_size) {
    const float* x   = (const float*)d_in[0];
    const float* w1  = (const float*)d_in[1];
    const float* b1  = (const float*)d_in[2];
    const float* g1  = (const float*)d_in[3];
    const float* be1 = (const float*)d_in[4];
    const float* m1  = (const float*)d_in[5];
    const float* rv1 = (const float*)d_in[6];
    const float* w2  = (const float*)d_in[7];
    const float* b2  = (const float*)d_in[8];
    const float* g2  = (const float*)d_in[9];
    const float* be2 = (const float*)d_in[10];
    const float* m2  = (const float*)d_in[11];
    const float* rv2 = (const float*)d_in[12];
    const float* wc  = (const float*)d_in[13];
    const float* bc  = (const float*)d_in[14];

    cudaFuncSetAttribute(snn_main, cudaFuncAttributeMaxDynamicSharedMemorySize, SM_BYTES);

    snn_main<<<NBLK, THREADS, SM_BYTES>>>(x, w1, b1, g1, be1, m1, rv1,
                                          w2, b2, g2, be2, m2, rv2,
                                          wc, bc, (float*)d_out);
}

// round 8
// speedup vs baseline: 2.5703x; 1.5499x over previous
#include <cuda_runtime.h>
#include <cuda_fp16.h>

#define FULL 0xFFFFFFFFu

constexpr int B  = 16;
constexpr int T  = 512;
constexpr int C  = 3;
constexpr int V  = 16;
constexpr int H  = 128;
constexpr int NC = 12;

constexpr int THREADS = 256;
constexpr int NWARPS  = 8;
constexpr int NBLK    = 444;            // 148 SMs * 3 blocks -> exactly one wave
constexpr int NTILES  = B * T;          // 8192 tiles; tile = one (b,t) row = 16 positions

// LIF1 closed-form thresholds (category = #thresholds passed; validated R6, rel_err 2.3e-5)
constexpr float TH3  = 2.0f / 3.0f;
constexpr float TH2p = 4.0f / 7.0f;
constexpr float TH1p = 8.0f / 15.0f;

// smem layout (bytes)
constexpr int W2_PITCH  = 136;                       // halfs/row, conflict-free ldmatrix
constexpr int IND_PITCH = 72;                        // halfs/row, conflict-free ldmatrix
constexpr int OFF_W2   = 0;                          // 128*136*2 = 34816
constexpr int OFF_IND  = OFF_W2 + H * W2_PITCH * 2;  // 128*72*2  = 18432
constexpr int OFF_C2   = OFF_IND + H * IND_PITCH * 2;
constexpr int OFF_INV2 = OFF_C2 + H * 4;
constexpr int SM_BYTES = OFF_INV2 + H * 4;           // ~54.3 KB -> 3 blocks/SM

__device__ float    g_acc[B * H];   // zero-init; reset by last block each call
__device__ unsigned g_ctr;          // ticket; reset by last block each call

__device__ __forceinline__ unsigned smem_u32(const void* p) {
    unsigned r;
    asm("{ .reg .u64 t; cvta.to.shared.u64 t, %1; cvt.u32.u64 %0, t; }" : "=r"(r) : "l"(p));
    return r;
}
__device__ __forceinline__ void ldmA4(unsigned* a, unsigned addr) {
    asm volatile("ldmatrix.sync.aligned.m8n8.x4.shared.b16 {%0,%1,%2,%3}, [%4];"
                 : "=r"(a[0]), "=r"(a[1]), "=r"(a[2]), "=r"(a[3]) : "r"(addr));
}
__device__ __forceinline__ void ldmBt2(unsigned& b0, unsigned& b1, unsigned addr) {
    asm volatile("ldmatrix.sync.aligned.m8n8.x2.trans.shared.b16 {%0,%1}, [%2];"
                 : "=r"(b0), "=r"(b1) : "r"(addr));
}
__device__ __forceinline__ void mma16816(float* d, const unsigned* a, unsigned b0, unsigned b1) {
    asm volatile("mma.sync.aligned.m16n8k16.row.col.f32.f16.f16.f32 "
                 "{%0,%1,%2,%3}, {%4,%5,%6,%7}, {%8,%9}, {%0,%1,%2,%3};"
                 : "+f"(d[0]), "+f"(d[1]), "+f"(d[2]), "+f"(d[3])
                 : "r"(a[0]), "r"(a[1]), "r"(a[2]), "r"(a[3]), "r"(b0), "r"(b1));
}

// branch-free LIF2 over 4 steps; h reconstructed from basis sums; returns spike count
__device__ __forceinline__ float lif2(float A, float Bb1, float Bb2, float Bb3, float cc) {
    float base = A + cc;
    float h2 = base + Bb3;
    float h3 = base + Bb2;
    float h4 = h2 + Bb1;

    float v = base * 0.5f;
    bool s = v >= 0.5f;
    int cnt = s;
    v = s ? 0.f : v;

    v = fmaf(h2 - v, 0.5f, v);
    s = v >= 0.5f; cnt += s; v = s ? 0.f : v;

    v = fmaf(h3 - v, 0.5f, v);
    s = v >= 0.5f; cnt += s; v = s ? 0.f : v;

    v = fmaf(h4 - v, 0.5f, v);
    cnt += (v >= 0.5f);
    return (float)cnt;
}

__global__ void __launch_bounds__(THREADS, 3)
snn_main(const float* __restrict__ x,
         const float* __restrict__ w1, const float* __restrict__ b1,
         const float* __restrict__ g1, const float* __restrict__ be1,
         const float* __restrict__ m1, const float* __restrict__ rv1,
         const float* __restrict__ w2, const float* __restrict__ b2,
         const float* __restrict__ g2, const float* __restrict__ be2,
         const float* __restrict__ m2, const float* __restrict__ rv2,
         const float* __restrict__ wc, const float* __restrict__ bc,
         float* __restrict__ out) {
    extern __shared__ __align__(16) unsigned char smraw[];
    __half* w2h   = reinterpret_cast<__half*>(smraw + OFF_W2);
    __half* ind   = reinterpret_cast<__half*>(smraw + OFF_IND);
    float*  c2s   = reinterpret_cast<float*>(smraw + OFF_C2);
    float*  inv2s = reinterpret_cast<float*>(smraw + OFF_INV2);

    const int tid  = threadIdx.x;
    const int warp = tid >> 5, lane = tid & 31;

    // ---- fold BN2; stage W2' as fp16, OUTPUT-channel-major rows (A operand) ----
    if (tid < H) {
        float inv2 = g2[tid] * rsqrtf(rv2[tid] + 1e-5f);
        inv2s[tid] = inv2;
        c2s[tid]   = (b2[tid] - m2[tid]) * inv2 + be2[tid];
    }
    __syncthreads();
    for (int i = tid; i < H * H; i += THREADS) {
        int p = i >> 7, o = i & 127;             // p = out channel (row), o = in channel (k)
        w2h[p * W2_PITCH + o] = __float2half_rn(w2[i] * inv2s[p]);   // R8 FIX: was transposed
    }
    __syncthreads();

    // ---- load stationary A fragments: warp w covers outchans 16w..16w+15 ----
    unsigned aF[8][4];
    {
        unsigned w2base = smem_u32(w2h);
        int r   = 16 * warp + (lane & 15);
        int ch8 = (lane >> 4) * 8;
#pragma unroll
        for (int kk = 0; kk < 8; kk++) {
            unsigned addr = w2base + (unsigned)((r * W2_PITCH) + kk * 16 + ch8) * 2u;
            ldmA4(aF[kk], addr);
        }
    }

    // ---- per-thread build params: channel = tid&127, position-half = tid>>7 ----
    const int mych = tid & 127;
    const int poshalf = tid >> 7;
    float w1a, w1b, w1c, c1v;
    {
        float inv1 = g1[mych] * rsqrtf(rv1[mych] + 1e-5f);
        w1a = w1[mych * 3 + 0] * inv1;
        w1b = w1[mych * 3 + 1] * inv1;
        w1c = w1[mych * 3 + 2] * inv1;
        c1v = (b1[mych] - m1[mych]) * inv1 + be1[mych];
    }
    // ---- epilogue params: lane -> quad q (outchan), pp (position-in-group) ----
    const int q  = lane >> 2;
    const int pp = lane & 3;
    const float c2Lo = c2s[16 * warp + q];
    const float c2Hi = c2s[16 * warp + q + 8];
    const unsigned indbase = smem_u32(ind);
    unsigned* indw = reinterpret_cast<unsigned*>(ind + mych * IND_PITCH);

    // ---- persistent tile loop: tile = (b, t-row) = 16 positions ----
    for (int tile = blockIdx.x; tile < NTILES; tile += NBLK) {
        const int bb = tile >> 9;
        const float* xr = x + (size_t)tile * (C * V);   // tile == b*T + trow

        __syncthreads();                                // prev tile's mma reads done
        // build indicator: 8 positions for (mych, poshalf); one-hot fp16 categories
#pragma unroll
        for (int j = 0; j < 8; j++) {
            int pa = poshalf * 8 + j;                   // position 0..15 (= v index)
            float x0 = xr[pa], x1 = xr[16 + pa], x2 = xr[32 + pa];
            float h = fmaf(w1a, x0, fmaf(w1b, x1, fmaf(w1c, x2, c1v)));
            bool s4 = h >= 1.0f;
            bool s3 = h >= TH3;
            bool s2 = h >= TH2p;
            bool s1 = h >= TH1p;
            unsigned pk0 = (s4 ? 0x3C00u : 0u) | ((s3 && !s4) ? 0x3C000000u : 0u); // cat4|cat3
            unsigned pk1 = ((s2 && !s3) ? 0x3C00u : 0u) | ((s1 && !s2) ? 0x3C000000u : 0u); // cat2|cat1
            int g = pa >> 2, pl = pa & 3;
            unsigned* wp = indw + (16 * g + 2 * pl) / 2;
            wp[0] = pk0;                                // cols 16g+2pl, +1
            wp[4] = pk1;                                // cols 16g+8+2pl, +1
        }
        __syncthreads();

        float cLo = 0.f, cHi = 0.f;
        const int rk = lane & 15;
#pragma unroll
        for (int g = 0; g < 4; g++) {
            float d0[4] = {0.f, 0.f, 0.f, 0.f};         // n-tile s=0: (cat4, cat3)
            float d1[4] = {0.f, 0.f, 0.f, 0.f};         // n-tile s=1: (cat2, cat1)
            unsigned badr = indbase + (unsigned)(rk * IND_PITCH + 16 * g) * 2u;
#pragma unroll
            for (int kk = 0; kk < 8; kk++) {
                unsigned b0, b1r, e0, e1r;
                unsigned ad = badr + (unsigned)(kk * 16 * IND_PITCH) * 2u;
                ldmBt2(b0, b1r, ad);
                ldmBt2(e0, e1r, ad + 16u);              // +8 half cols
                mma16816(d0, aF[kk], b0, b1r);
                mma16816(d1, aF[kk], e0, e1r);
            }
            // lane holds pos 4g+pp, outchans 16w+q (d[0],d[1]) and 16w+q+8 (d[2],d[3])
            cLo += lif2(d0[0], d1[1], d1[0], d0[1], c2Lo);
            cHi += lif2(d0[2], d1[3], d1[2], d0[3], c2Hi);
        }
        // reduce over the 4 lanes of the quad (positions), flush per tile
        cLo += __shfl_xor_sync(FULL, cLo, 1); cLo += __shfl_xor_sync(FULL, cLo, 2);
        cHi += __shfl_xor_sync(FULL, cHi, 1); cHi += __shfl_xor_sync(FULL, cHi, 2);
        if (pp == 0) {                                  // exact integer-valued fp32 adds
            atomicAdd(&g_acc[bb * H + 16 * warp + q], cLo);
            atomicAdd(&g_acc[bb * H + 16 * warp + q + 8], cHi);
        }
    }

    // ---- last-block epilogue: feat -> classifier, reset state ----
    __shared__ unsigned s_ticket;
    __threadfence();
    __syncthreads();
    if (tid == 0) s_ticket = atomicAdd(&g_ctr, 1u);
    __syncthreads();
    if (s_ticket == NBLK - 1) {
        __threadfence();
        float* feat = reinterpret_cast<float*>(smraw + OFF_IND);  // reuse indicator area
        for (int i = tid; i < B * H; i += THREADS) {
            float v = __ldcg(&g_acc[i]);
            feat[i] = v * (1.f / (4.f * (float)(T * V)));
            g_acc[i] = 0.f;                             // reset for next call
        }
        __syncthreads();
        if (tid < B * NC) {
            int b = tid / NC, n = tid % NC;
            float s = bc[n];
#pragma unroll 8
            for (int pch = 0; pch < H; pch++)
                s = fmaf(wc[n * H + pch], feat[b * H + pch], s);
            out[b * NC + n] = s;
        }
        if (tid == 0) atomicExch(&g_ctr, 0u);           // reset for next call
    }
}

extern "C" void kernel_launch(void* const* d_in, const int* in_sizes, int n_in,
                              void* d_out, int out_size) {
    const float* x   = (const float*)d_in[0];
    const float* w1  = (const float*)d_in[1];
    const float* b1  = (const float*)d_in[2];
    const float* g1  = (const float*)d_in[3];
    const float* be1 = (const float*)d_in[4];
    const float* m1  = (const float*)d_in[5];
    const float* rv1 = (const float*)d_in[6];
    const float* w2  = (const float*)d_in[7];
    const float* b2  = (const float*)d_in[8];
    const float* g2  = (const float*)d_in[9];
    const float* be2 = (const float*)d_in[10];
    const float* m2  = (const float*)d_in[11];
    const float* rv2 = (const float*)d_in[12];
    const float* wc  = (const float*)d_in[13];
    const float* bc  = (const float*)d_in[14];

    cudaFuncSetAttribute(snn_main, cudaFuncAttributeMaxDynamicSharedMemorySize, SM_BYTES);

    snn_main<<<NBLK, THREADS, SM_BYTES>>>(x, w1, b1, g1, be1, m1, rv1,
                                          w2, b2, g2, be2, m2, rv2,
                                          wc, bc, (float*)d_out);
}